// round 7
// baseline (speedup 1.0000x reference)
#include <cuda_runtime.h>
#include <cstdint>
#include <math.h>

#define B 32
#define T_DEC 1024
#define T_SRC 2048
#define D 1024

#define BM 128
#define BN 128
#define BK 16
#define LDS_W (BM + 4)   // padded to break store bank conflicts; even -> 8B aligned pair reads

// ---------- packed f32x2 helpers (sm_103a FFMA2) ----------
__device__ __forceinline__ unsigned long long pack2(float lo, float hi) {
    unsigned long long r;
    asm("mov.b64 %0, {%1, %2};" : "=l"(r) : "f"(lo), "f"(hi));
    return r;
}
__device__ __forceinline__ void ffma2(unsigned long long& acc, unsigned long long a, unsigned long long b) {
    asm("fma.rn.f32x2 %0, %1, %2, %0;" : "+l"(acc) : "l"(a), "l"(b));
}

// ============================================================================
// Kernel 1: scores S[b,t,s] = sum_d Q[b,t,d] * K[b,s,d]   (NT GEMM, both K-major)
// ============================================================================
__global__ __launch_bounds__(256, 2)
void scores_kernel(const float* __restrict__ Q, const float* __restrict__ K,
                   float* __restrict__ S)
{
    __shared__ float As[BK][LDS_W];
    __shared__ float Bs[BK][LDS_W];

    const int b       = blockIdx.z;
    const int rowBase = blockIdx.y * BM;   // t
    const int colBase = blockIdx.x * BN;   // s

    const float* Qb = Q + (size_t)b * T_DEC * D + (size_t)rowBase * D;
    const float* Kb = K + (size_t)b * T_SRC * D + (size_t)colBase * D;
    float*       Sb = S + (size_t)b * T_DEC * T_SRC;

    const int tid = threadIdx.x;
    const int tx  = tid & 15;
    const int ty  = tid >> 4;

    const int p0 = tid;
    const int p1 = tid + 256;
    const int r0 = p0 >> 2, kq0 = (p0 & 3) * 4;
    const int r1 = p1 >> 2, kq1 = (p1 & 3) * 4;

    unsigned long long acc[8][4];
    #pragma unroll
    for (int i = 0; i < 8; i++)
        #pragma unroll
        for (int j = 0; j < 4; j++) acc[i][j] = 0ull;

    for (int kt = 0; kt < D; kt += BK) {
        // load A tile (128 x 16), transposed into As[k][row]
        {
            float4 v = *(const float4*)(Qb + (size_t)r0 * D + kt + kq0);
            As[kq0+0][r0] = v.x; As[kq0+1][r0] = v.y; As[kq0+2][r0] = v.z; As[kq0+3][r0] = v.w;
            v = *(const float4*)(Qb + (size_t)r1 * D + kt + kq1);
            As[kq1+0][r1] = v.x; As[kq1+1][r1] = v.y; As[kq1+2][r1] = v.z; As[kq1+3][r1] = v.w;
        }
        // load B tile (128 x 16), transposed into Bs[k][col]
        {
            float4 v = *(const float4*)(Kb + (size_t)r0 * D + kt + kq0);
            Bs[kq0+0][r0] = v.x; Bs[kq0+1][r0] = v.y; Bs[kq0+2][r0] = v.z; Bs[kq0+3][r0] = v.w;
            v = *(const float4*)(Kb + (size_t)r1 * D + kt + kq1);
            Bs[kq1+0][r1] = v.x; Bs[kq1+1][r1] = v.y; Bs[kq1+2][r1] = v.z; Bs[kq1+3][r1] = v.w;
        }
        __syncthreads();

        #pragma unroll
        for (int k = 0; k < BK; k++) {
            unsigned long long bfrag[4];
            const unsigned long long* bp =
                (const unsigned long long*)&Bs[k][tx * 8];
            #pragma unroll
            for (int j = 0; j < 4; j++) bfrag[j] = bp[j];
            #pragma unroll
            for (int i = 0; i < 8; i++) {
                float a = As[k][ty * 8 + i];
                unsigned long long a2 = pack2(a, a);
                #pragma unroll
                for (int j = 0; j < 4; j++) ffma2(acc[i][j], a2, bfrag[j]);
            }
        }
        __syncthreads();
    }

    #pragma unroll
    for (int i = 0; i < 8; i++) {
        unsigned long long* out = (unsigned long long*)
            (Sb + (size_t)(rowBase + ty * 8 + i) * T_SRC + colBase + tx * 8);
        #pragma unroll
        for (int j = 0; j < 4; j++) out[j] = acc[i][j];
    }
}

// ============================================================================
// Kernel 2: masked softmax over last dim, in place. One block per (b,t) row.
// Mask is int32 (bool inputs are materialized as int32 by the harness;
// reading fp32 1.0f/0.0f as int also yields nonzero/zero, so this is robust).
// ============================================================================
__device__ __forceinline__ float warpRedMax(float v) {
    #pragma unroll
    for (int o = 16; o > 0; o >>= 1) v = fmaxf(v, __shfl_xor_sync(0xffffffffu, v, o));
    return v;
}
__device__ __forceinline__ float warpRedSum(float v) {
    #pragma unroll
    for (int o = 16; o > 0; o >>= 1) v += __shfl_xor_sync(0xffffffffu, v, o);
    return v;
}

__global__ __launch_bounds__(256)
void softmax_kernel(float* __restrict__ S, const int* __restrict__ M)
{
    __shared__ float red[8];
    const int row = blockIdx.x;           // b*T_DEC + t
    const int b   = row / T_DEC;
    float* x = S + (size_t)row * T_SRC;
    const int* m = M + (size_t)b * T_SRC;

    const int tid  = threadIdx.x;
    const int lane = tid & 31;
    const int wid  = tid >> 5;

    float v[8];
    float mx = -INFINITY;
    #pragma unroll
    for (int i = 0; i < 8; i++) {
        int s = tid + i * 256;
        float val = x[s];
        v[i] = (m[s] != 0) ? val : -INFINITY;
        mx = fmaxf(mx, v[i]);
    }
    mx = warpRedMax(mx);
    if (lane == 0) red[wid] = mx;
    __syncthreads();
    if (wid == 0) {
        float t = (lane < 8) ? red[lane] : -INFINITY;  // no duplicate reads
        t = warpRedMax(t);
        if (lane == 0) red[0] = t;
    }
    __syncthreads();
    mx = red[0];

    float sum = 0.f;
    #pragma unroll
    for (int i = 0; i < 8; i++) {
        float e = __expf(v[i] - mx);   // -inf -> 0
        v[i] = e;
        sum += e;
    }
    sum = warpRedSum(sum);
    __syncthreads();
    if (lane == 0) red[wid] = sum;
    __syncthreads();
    if (wid == 0) {
        float t = (lane < 8) ? red[lane] : 0.0f;       // FIX: was red[lane & 7],
        t = warpRedSum(t);                              // which counted each
        if (lane == 0) red[0] = t;                      // partial sum 4x
    }
    __syncthreads();
    const float inv = 1.0f / red[0];

    #pragma unroll
    for (int i = 0; i < 8; i++) {
        int s = tid + i * 256;
        x[s] = v[i] * inv;
    }
}

// ============================================================================
// Kernel 3: context C[b,t,d] = sum_s W[b,t,s] * V[b,s,d]   (NN GEMM)
// ============================================================================
__global__ __launch_bounds__(256, 2)
void context_kernel(const float* __restrict__ W, const float* __restrict__ V,
                    float* __restrict__ C)
{
    __shared__ float As[BK][LDS_W];   // W tile, transposed: As[k][t]
    __shared__ float Bs[BK][LDS_W];   // V tile, natural:    Bs[k][d]

    const int b       = blockIdx.z;
    const int rowBase = blockIdx.y * BM;   // t
    const int colBase = blockIdx.x * BN;   // d

    const float* Wb = W + (size_t)b * T_DEC * T_SRC + (size_t)rowBase * T_SRC;
    const float* Vb = V + (size_t)b * T_SRC * D + colBase;
    float*       Cb = C + (size_t)b * T_DEC * D;

    const int tid = threadIdx.x;
    const int tx  = tid & 15;
    const int ty  = tid >> 4;

    const int p0 = tid;
    const int p1 = tid + 256;
    // A loader: row = p/4, kq = (p%4)*4
    const int ar0 = p0 >> 2, akq0 = (p0 & 3) * 4;
    const int ar1 = p1 >> 2, akq1 = (p1 & 3) * 4;
    // B loader: row = p/32 (k), col = (p%32)*4
    const int br0 = p0 >> 5, bc0 = (p0 & 31) * 4;
    const int br1 = p1 >> 5, bc1 = (p1 & 31) * 4;

    unsigned long long acc[8][4];
    #pragma unroll
    for (int i = 0; i < 8; i++)
        #pragma unroll
        for (int j = 0; j < 4; j++) acc[i][j] = 0ull;

    for (int kt = 0; kt < T_SRC; kt += BK) {
        {
            float4 v = *(const float4*)(Wb + (size_t)ar0 * T_SRC + kt + akq0);
            As[akq0+0][ar0] = v.x; As[akq0+1][ar0] = v.y; As[akq0+2][ar0] = v.z; As[akq0+3][ar0] = v.w;
            v = *(const float4*)(Wb + (size_t)ar1 * T_SRC + kt + akq1);
            As[akq1+0][ar1] = v.x; As[akq1+1][ar1] = v.y; As[akq1+2][ar1] = v.z; As[akq1+3][ar1] = v.w;
        }
        {
            float4 v = *(const float4*)(Vb + (size_t)(kt + br0) * D + bc0);
            *(float4*)&Bs[br0][bc0] = v;
            v = *(const float4*)(Vb + (size_t)(kt + br1) * D + bc1);
            *(float4*)&Bs[br1][bc1] = v;
        }
        __syncthreads();

        #pragma unroll
        for (int k = 0; k < BK; k++) {
            unsigned long long bfrag[4];
            const unsigned long long* bp =
                (const unsigned long long*)&Bs[k][tx * 8];
            #pragma unroll
            for (int j = 0; j < 4; j++) bfrag[j] = bp[j];
            #pragma unroll
            for (int i = 0; i < 8; i++) {
                float a = As[k][ty * 8 + i];
                unsigned long long a2 = pack2(a, a);
                #pragma unroll
                for (int j = 0; j < 4; j++) ffma2(acc[i][j], a2, bfrag[j]);
            }
        }
        __syncthreads();
    }

    #pragma unroll
    for (int i = 0; i < 8; i++) {
        unsigned long long* out = (unsigned long long*)
            (Cb + (size_t)(rowBase + ty * 8 + i) * D + colBase + tx * 8);
        #pragma unroll
        for (int j = 0; j < 4; j++) out[j] = acc[i][j];
    }
}

// ============================================================================
// Launch
// ============================================================================
extern "C" void kernel_launch(void* const* d_in, const int* in_sizes, int n_in,
                              void* d_out, int out_size)
{
    (void)in_sizes; (void)n_in; (void)out_size;
    const float* dec  = (const float*)d_in[0];          // [B, T_DEC, D]
    const float* enc  = (const float*)d_in[1];          // [B, T_SRC, D]
    const int*   mask = (const int*)d_in[2];            // [B, 1, T_SRC] bool -> int32

    float* ctx  = (float*)d_out;                                // [B, T_DEC, D]
    float* attn = (float*)d_out + (size_t)B * T_DEC * D;        // [B, T_DEC, T_SRC]

    dim3 g1(T_SRC / BN, T_DEC / BM, B);
    scores_kernel<<<g1, 256>>>(dec, enc, attn);

    softmax_kernel<<<B * T_DEC, 256>>>(attn, mask);

    dim3 g2(D / BN, T_DEC / BM, B);
    context_kernel<<<g2, 256>>>(attn, enc, ctx);
}

// round 9
// speedup vs baseline: 2.3486x; 2.3486x over previous
#include <cuda_runtime.h>
#include <cuda_bf16.h>
#include <cstdint>
#include <math.h>

#define B 32
#define T_DEC 1024
#define T_SRC 2048
#define D 1024

// ============================================================================
// mma.sync / ldmatrix helpers (compute_103-safe: sm_80+ PTX only)
// ============================================================================
__device__ __forceinline__ uint32_t smem_u32(const void* p) {
    uint32_t a;
    asm("{ .reg .u64 t; cvta.to.shared.u64 t, %1; cvt.u32.u64 %0, t; }" : "=r"(a) : "l"(p));
    return a;
}
__device__ __forceinline__ void ldsm_x4(uint32_t r[4], uint32_t addr) {
    asm volatile("ldmatrix.sync.aligned.m8n8.x4.shared.b16 {%0,%1,%2,%3}, [%4];"
                 : "=r"(r[0]), "=r"(r[1]), "=r"(r[2]), "=r"(r[3]) : "r"(addr));
}
__device__ __forceinline__ void ldsm_x2(uint32_t r[2], uint32_t addr) {
    asm volatile("ldmatrix.sync.aligned.m8n8.x2.shared.b16 {%0,%1}, [%2];"
                 : "=r"(r[0]), "=r"(r[1]) : "r"(addr));
}
__device__ __forceinline__ void ldsm_x2t(uint32_t r[2], uint32_t addr) {
    asm volatile("ldmatrix.sync.aligned.m8n8.x2.trans.shared.b16 {%0,%1}, [%2];"
                 : "=r"(r[0]), "=r"(r[1]) : "r"(addr));
}
__device__ __forceinline__ void mma_bf16(float d[4], const uint32_t a[4], const uint32_t b[2]) {
    asm volatile(
        "mma.sync.aligned.m16n8k16.row.col.f32.bf16.bf16.f32 "
        "{%0,%1,%2,%3}, {%4,%5,%6,%7}, {%8,%9}, {%0,%1,%2,%3};"
        : "+f"(d[0]), "+f"(d[1]), "+f"(d[2]), "+f"(d[3])
        : "r"(a[0]), "r"(a[1]), "r"(a[2]), "r"(a[3]), "r"(b[0]), "r"(b[1]));
}

// split fp32 -> (hi, lo) bf16 pairs, packed 2-at-a-time into b32
__device__ __forceinline__ void split2(float x0, float x1, uint32_t& h, uint32_t& l) {
    __nv_bfloat16 h0 = __float2bfloat16(x0);
    __nv_bfloat16 h1 = __float2bfloat16(x1);
    __nv_bfloat16 l0 = __float2bfloat16(x0 - __bfloat162float(h0));
    __nv_bfloat16 l1 = __float2bfloat16(x1 - __bfloat162float(h1));
    __nv_bfloat162 hp = __nv_bfloat162(h0, h1);
    __nv_bfloat162 lp = __nv_bfloat162(l0, l1);
    h = *(uint32_t*)&hp;
    l = *(uint32_t*)&lp;
}

// ============================================================================
// Split-bf16 GEMM via mma.sync:  C[m,n] = sum_k A[m,k] * B(k,n)
//   BTRANS=false: B stored [n][k] (k contiguous)  -> NT (scores: B=enc[s,d])
//   BTRANS=true : B stored [k][n] (n contiguous)  -> NN (context: B=enc[s,d], k=s)
// CTA tile 128x128, BK=32, 8 warps (2x4), warp tile 64x32, double-buffered.
// ============================================================================
#define BK 32
#define A_ST 40                       // padded row stride (elems) for [128][32] tiles
#define BNN_ST 136                    // padded row stride (elems) for [32][128] tile
#define A_BYTES (128 * A_ST * 2)      // 10240
#define OFF_AH 0
#define OFF_AL (A_BYTES)
#define OFF_BH (2 * A_BYTES)
#define OFF_BL (3 * A_BYTES)
#define STAGE  (4 * A_BYTES)          // 40960
#define GEMM_SMEM (2 * STAGE)         // 81920

template <bool BTRANS>
__global__ __launch_bounds__(256, 1)
void gemm_split(const float* __restrict__ A, const float* __restrict__ Bm,
                float* __restrict__ C,
                int lda, int ldb, int ldc, int KK,
                size_t sA, size_t sB, size_t sC)
{
    extern __shared__ char dsm[];
    const uint32_t sbase = smem_u32(dsm);

    const int bz      = blockIdx.z;
    const int rowBase = blockIdx.y * 128;
    const int colBase = blockIdx.x * 128;

    const float* Ab = A  + (size_t)bz * sA + (size_t)rowBase * lda;
    const float* Bb = BTRANS ? (Bm + (size_t)bz * sB + colBase)
                             : (Bm + (size_t)bz * sB + (size_t)colBase * ldb);
    float*       Cb = C  + (size_t)bz * sC;

    const int tid  = threadIdx.x;
    const int lane = tid & 31;
    const int wid  = tid >> 5;
    const int m0   = (wid & 1) * 64;      // warp M offset
    const int n0   = (wid >> 1) * 32;     // warp N offset

    float acc[4][4][4];
    #pragma unroll
    for (int i = 0; i < 4; i++)
        #pragma unroll
        for (int j = 0; j < 4; j++)
            #pragma unroll
            for (int r = 0; r < 4; r++) acc[i][j][r] = 0.f;

    const int nch = KK / BK;
    float4 ra[4], rb[4];

    // ---- loaders ----
    auto load_regs = [&](int c) {
        const int kt = c * BK;
        #pragma unroll
        for (int q = 0; q < 4; q++) {
            const int f4 = tid + q * 256;
            { // A: [128][32]
                const int row = f4 >> 3, kq = (f4 & 7) * 4;
                ra[q] = *(const float4*)(Ab + (size_t)row * lda + kt + kq);
            }
            if (!BTRANS) { // B: [128 n][32 k]
                const int row = f4 >> 3, kq = (f4 & 7) * 4;
                rb[q] = *(const float4*)(Bb + (size_t)row * ldb + kt + kq);
            } else {       // B: [32 k][128 n]
                const int kr = f4 >> 5, nq = (f4 & 31) * 4;
                rb[q] = *(const float4*)(Bb + (size_t)(kt + kr) * ldb + nq);
            }
        }
    };
    auto store_stage = [&](int c) {
        char* st = dsm + (c & 1) * STAGE;
        #pragma unroll
        for (int q = 0; q < 4; q++) {
            const int f4 = tid + q * 256;
            {
                const int row = f4 >> 3, kq = (f4 & 7) * 4;
                uint32_t h01, l01, h23, l23;
                split2(ra[q].x, ra[q].y, h01, l01);
                split2(ra[q].z, ra[q].w, h23, l23);
                const int off = (row * A_ST + kq) * 2;
                *(uint2*)(st + OFF_AH + off) = make_uint2(h01, h23);
                *(uint2*)(st + OFF_AL + off) = make_uint2(l01, l23);
            }
            {
                uint32_t h01, l01, h23, l23;
                split2(rb[q].x, rb[q].y, h01, l01);
                split2(rb[q].z, rb[q].w, h23, l23);
                int off;
                if (!BTRANS) { const int row = f4 >> 3, kq = (f4 & 7) * 4; off = (row * A_ST + kq) * 2; }
                else         { const int kr = f4 >> 5, nq = (f4 & 31) * 4; off = (kr * BNN_ST + nq) * 2; }
                *(uint2*)(st + OFF_BH + off) = make_uint2(h01, h23);
                *(uint2*)(st + OFF_BL + off) = make_uint2(l01, l23);
            }
        }
    };

    load_regs(0);
    store_stage(0);

    for (int c = 0; c < nch; c++) {
        __syncthreads();                       // stage c&1 visible
        if (c + 1 < nch) load_regs(c + 1);     // prefetch overlaps MMAs

        const uint32_t stg = sbase + (c & 1) * STAGE;
        #pragma unroll
        for (int ks = 0; ks < 2; ks++) {
            const int k0 = ks * 16;
            uint32_t ah[4][4], al[4][4], bh[4][2], bl[4][2];
            #pragma unroll
            for (int im = 0; im < 4; im++) {
                const uint32_t ad = stg + OFF_AH +
                    ((m0 + im * 16 + (lane & 15)) * A_ST + k0 + ((lane >> 4) & 1) * 8) * 2;
                ldsm_x4(ah[im], ad);
                ldsm_x4(al[im], ad + (OFF_AL - OFF_AH));
            }
            #pragma unroll
            for (int jn = 0; jn < 4; jn++) {
                const int i16 = lane & 15;
                uint32_t bd;
                if (!BTRANS) {
                    bd = stg + OFF_BH +
                        ((n0 + jn * 8 + (i16 & 7)) * A_ST + k0 + ((i16 >> 3) & 1) * 8) * 2;
                    ldsm_x2(bh[jn], bd);
                    ldsm_x2(bl[jn], bd + (OFF_BL - OFF_BH));
                } else {
                    bd = stg + OFF_BH +
                        ((k0 + (i16 & 7) + ((i16 >> 3) & 1) * 8) * BNN_ST + n0 + jn * 8) * 2;
                    ldsm_x2t(bh[jn], bd);
                    ldsm_x2t(bl[jn], bd + (OFF_BL - OFF_BH));
                }
            }
            #pragma unroll
            for (int im = 0; im < 4; im++)
                #pragma unroll
                for (int jn = 0; jn < 4; jn++) {
                    mma_bf16(acc[im][jn], ah[im], bh[jn]);   // hi*hi
                    mma_bf16(acc[im][jn], ah[im], bl[jn]);   // hi*lo
                    mma_bf16(acc[im][jn], al[im], bh[jn]);   // lo*hi
                }
        }

        __syncthreads();                       // all warps done reading other stage
        if (c + 1 < nch) store_stage(c + 1);
    }

    // ---- epilogue ----
    const int r  = lane >> 2;
    const int cp = (lane & 3) * 2;
    #pragma unroll
    for (int im = 0; im < 4; im++) {
        #pragma unroll
        for (int jn = 0; jn < 4; jn++) {
            const int row = rowBase + m0 + im * 16 + r;
            const int col = colBase + n0 + jn * 8 + cp;
            *(float2*)(Cb + (size_t)row * ldc + col)       = make_float2(acc[im][jn][0], acc[im][jn][1]);
            *(float2*)(Cb + (size_t)(row + 8) * ldc + col) = make_float2(acc[im][jn][2], acc[im][jn][3]);
        }
    }
}

// ============================================================================
// Masked softmax over last dim, in place. One block per (b,t) row.
// ============================================================================
__device__ __forceinline__ float warpRedMax(float v) {
    #pragma unroll
    for (int o = 16; o > 0; o >>= 1) v = fmaxf(v, __shfl_xor_sync(0xffffffffu, v, o));
    return v;
}
__device__ __forceinline__ float warpRedSum(float v) {
    #pragma unroll
    for (int o = 16; o > 0; o >>= 1) v += __shfl_xor_sync(0xffffffffu, v, o);
    return v;
}

__global__ __launch_bounds__(256)
void softmax_kernel(float* __restrict__ S, const int* __restrict__ M)
{
    __shared__ float red[8];
    const int row = blockIdx.x;
    const int b   = row / T_DEC;
    float* x = S + (size_t)row * T_SRC;
    const int* m = M + (size_t)b * T_SRC;

    const int tid  = threadIdx.x;
    const int lane = tid & 31;
    const int wid  = tid >> 5;

    float v[8];
    float mx = -INFINITY;
    #pragma unroll
    for (int i = 0; i < 8; i++) {
        int s = tid + i * 256;
        float val = x[s];
        v[i] = (m[s] != 0) ? val : -INFINITY;
        mx = fmaxf(mx, v[i]);
    }
    mx = warpRedMax(mx);
    if (lane == 0) red[wid] = mx;
    __syncthreads();
    if (wid == 0) {
        float t = (lane < 8) ? red[lane] : -INFINITY;
        t = warpRedMax(t);
        if (lane == 0) red[0] = t;
    }
    __syncthreads();
    mx = red[0];

    float sum = 0.f;
    #pragma unroll
    for (int i = 0; i < 8; i++) {
        float e = __expf(v[i] - mx);
        v[i] = e;
        sum += e;
    }
    sum = warpRedSum(sum);
    __syncthreads();
    if (lane == 0) red[wid] = sum;
    __syncthreads();
    if (wid == 0) {
        float t = (lane < 8) ? red[lane] : 0.0f;
        t = warpRedSum(t);
        if (lane == 0) red[0] = t;
    }
    __syncthreads();
    const float inv = 1.0f / red[0];

    #pragma unroll
    for (int i = 0; i < 8; i++) {
        int s = tid + i * 256;
        x[s] = v[i] * inv;
    }
}

// ============================================================================
// Launch
// ============================================================================
extern "C" void kernel_launch(void* const* d_in, const int* in_sizes, int n_in,
                              void* d_out, int out_size)
{
    (void)in_sizes; (void)n_in; (void)out_size;
    const float* dec  = (const float*)d_in[0];   // [B, T_DEC, D]
    const float* enc  = (const float*)d_in[1];   // [B, T_SRC, D]
    const int*   mask = (const int*)d_in[2];     // [B, 1, T_SRC] bool -> int32

    float* ctx  = (float*)d_out;                              // [B, T_DEC, D]
    float* attn = (float*)d_out + (size_t)B * T_DEC * D;      // [B, T_DEC, T_SRC]

    cudaFuncSetAttribute(gemm_split<false>,
                         cudaFuncAttributeMaxDynamicSharedMemorySize, GEMM_SMEM);
    cudaFuncSetAttribute(gemm_split<true>,
                         cudaFuncAttributeMaxDynamicSharedMemorySize, GEMM_SMEM);

    // 1) scores = dec x enc^T   [M=T_DEC, N=T_SRC, K=D]   (B = enc[s,d], k-major)
    gemm_split<false><<<dim3(T_SRC / 128, T_DEC / 128, B), 256, GEMM_SMEM>>>(
        dec, enc, attn, D, D, T_SRC, D,
        (size_t)T_DEC * D, (size_t)T_SRC * D, (size_t)T_DEC * T_SRC);

    // 2) masked softmax in place
    softmax_kernel<<<B * T_DEC, 256>>>(attn, mask);

    // 3) context = attn x enc   [M=T_DEC, N=D, K=T_SRC]   (B = enc[s,d], n-major)
    gemm_split<true><<<dim3(D / 128, T_DEC / 128, B), 256, GEMM_SMEM>>>(
        attn, enc, ctx, T_SRC, D, D, T_SRC,
        (size_t)T_DEC * T_SRC, (size_t)T_SRC * D, (size_t)T_DEC * D);
}

// round 10
// speedup vs baseline: 2.3909x; 1.0180x over previous
#include <cuda_runtime.h>
#include <cuda_bf16.h>
#include <cstdint>
#include <math.h>

#define B 32
#define T_DEC 1024
#define T_SRC 2048
#define D 1024

// ============================================================================
// mma.sync / ldmatrix helpers (compute_103-safe: sm_80+ PTX only)
// ============================================================================
__device__ __forceinline__ uint32_t smem_u32(const void* p) {
    uint32_t a;
    asm("{ .reg .u64 t; cvta.to.shared.u64 t, %1; cvt.u32.u64 %0, t; }" : "=r"(a) : "l"(p));
    return a;
}
__device__ __forceinline__ void ldsm_x4(uint32_t r[4], uint32_t addr) {
    asm volatile("ldmatrix.sync.aligned.m8n8.x4.shared.b16 {%0,%1,%2,%3}, [%4];"
                 : "=r"(r[0]), "=r"(r[1]), "=r"(r[2]), "=r"(r[3]) : "r"(addr));
}
__device__ __forceinline__ void ldsm_x4t(uint32_t r[4], uint32_t addr) {
    asm volatile("ldmatrix.sync.aligned.m8n8.x4.trans.shared.b16 {%0,%1,%2,%3}, [%4];"
                 : "=r"(r[0]), "=r"(r[1]), "=r"(r[2]), "=r"(r[3]) : "r"(addr));
}
__device__ __forceinline__ void mma_bf16(float d[4], const uint32_t a[4], const uint32_t b[2]) {
    asm volatile(
        "mma.sync.aligned.m16n8k16.row.col.f32.bf16.bf16.f32 "
        "{%0,%1,%2,%3}, {%4,%5,%6,%7}, {%8,%9}, {%0,%1,%2,%3};"
        : "+f"(d[0]), "+f"(d[1]), "+f"(d[2]), "+f"(d[3])
        : "r"(a[0]), "r"(a[1]), "r"(a[2]), "r"(a[3]), "r"(b[0]), "r"(b[1]));
}

// split fp32 -> (hi, lo) bf16 pairs, packed 2-at-a-time into b32
__device__ __forceinline__ void split2(float x0, float x1, uint32_t& h, uint32_t& l) {
    __nv_bfloat16 h0 = __float2bfloat16(x0);
    __nv_bfloat16 h1 = __float2bfloat16(x1);
    __nv_bfloat16 l0 = __float2bfloat16(x0 - __bfloat162float(h0));
    __nv_bfloat16 l1 = __float2bfloat16(x1 - __bfloat162float(h1));
    __nv_bfloat162 hp = __nv_bfloat162(h0, h1);
    __nv_bfloat162 lp = __nv_bfloat162(l0, l1);
    h = *(uint32_t*)&hp;
    l = *(uint32_t*)&lp;
}

// ============================================================================
// Split-bf16 GEMM via mma.sync:  C[m,n] = sum_k A[m,k] * B(k,n)
//   BTRANS=false: B stored [n][k] (k contiguous)  -> NT (scores: B=enc[s,d])
//   BTRANS=true : B stored [k][n] (n contiguous)  -> NN (context: B=enc[s,d], k=s)
// CTA tile 128x128, BK=32, 8 warps (2x4), warp tile 64x32, double-buffered,
// ONE barrier per chunk, x4 ldmatrix everywhere.
// ============================================================================
#define BK 32
#define A_ST 40                       // padded row stride (elems) for [128][32] tiles
#define BNN_ST 136                    // padded row stride (elems) for [32][128] tile
#define A_BYTES (128 * A_ST * 2)      // 10240
#define OFF_AH 0
#define OFF_AL (A_BYTES)
#define OFF_BH (2 * A_BYTES)
#define OFF_BL (3 * A_BYTES)
#define STAGE  (4 * A_BYTES)          // 40960
#define GEMM_SMEM (2 * STAGE)         // 81920

template <bool BTRANS>
__global__ __launch_bounds__(256, 1)
void gemm_split(const float* __restrict__ A, const float* __restrict__ Bm,
                float* __restrict__ C,
                int lda, int ldb, int ldc, int KK,
                size_t sA, size_t sB, size_t sC)
{
    extern __shared__ char dsm[];
    const uint32_t sbase = smem_u32(dsm);

    const int bz      = blockIdx.z;
    const int rowBase = blockIdx.y * 128;
    const int colBase = blockIdx.x * 128;

    const float* Ab = A  + (size_t)bz * sA + (size_t)rowBase * lda;
    const float* Bb = BTRANS ? (Bm + (size_t)bz * sB + colBase)
                             : (Bm + (size_t)bz * sB + (size_t)colBase * ldb);
    float*       Cb = C  + (size_t)bz * sC;

    const int tid  = threadIdx.x;
    const int lane = tid & 31;
    const int wid  = tid >> 5;
    const int m0   = (wid & 1) * 64;      // warp M offset
    const int n0   = (wid >> 1) * 32;     // warp N offset

    float acc[4][4][4];
    #pragma unroll
    for (int i = 0; i < 4; i++)
        #pragma unroll
        for (int j = 0; j < 4; j++)
            #pragma unroll
            for (int r = 0; r < 4; r++) acc[i][j][r] = 0.f;

    const int nch = KK / BK;
    float4 ra[4], rb[4];

    // ---- loaders ----
    auto load_regs = [&](int c) {
        const int kt = c * BK;
        #pragma unroll
        for (int q = 0; q < 4; q++) {
            const int f4 = tid + q * 256;
            { // A: [128][32]
                const int row = f4 >> 3, kq = (f4 & 7) * 4;
                ra[q] = *(const float4*)(Ab + (size_t)row * lda + kt + kq);
            }
            if (!BTRANS) { // B: [128 n][32 k]
                const int row = f4 >> 3, kq = (f4 & 7) * 4;
                rb[q] = *(const float4*)(Bb + (size_t)row * ldb + kt + kq);
            } else {       // B: [32 k][128 n]
                const int kr = f4 >> 5, nq = (f4 & 31) * 4;
                rb[q] = *(const float4*)(Bb + (size_t)(kt + kr) * ldb + nq);
            }
        }
    };
    auto store_stage = [&](int c) {
        char* st = dsm + (c & 1) * STAGE;
        #pragma unroll
        for (int q = 0; q < 4; q++) {
            const int f4 = tid + q * 256;
            {
                const int row = f4 >> 3, kq = (f4 & 7) * 4;
                uint32_t h01, l01, h23, l23;
                split2(ra[q].x, ra[q].y, h01, l01);
                split2(ra[q].z, ra[q].w, h23, l23);
                const int off = (row * A_ST + kq) * 2;
                *(uint2*)(st + OFF_AH + off) = make_uint2(h01, h23);
                *(uint2*)(st + OFF_AL + off) = make_uint2(l01, l23);
            }
            {
                uint32_t h01, l01, h23, l23;
                split2(rb[q].x, rb[q].y, h01, l01);
                split2(rb[q].z, rb[q].w, h23, l23);
                int off;
                if (!BTRANS) { const int row = f4 >> 3, kq = (f4 & 7) * 4; off = (row * A_ST + kq) * 2; }
                else         { const int kr = f4 >> 5, nq = (f4 & 31) * 4; off = (kr * BNN_ST + nq) * 2; }
                *(uint2*)(st + OFF_BH + off) = make_uint2(h01, h23);
                *(uint2*)(st + OFF_BL + off) = make_uint2(l01, l23);
            }
        }
    };

    load_regs(0);
    store_stage(0);

    for (int c = 0; c < nch; c++) {
        // Single barrier per chunk: proves (a) stage c&1 fully written,
        // (b) every warp finished chunk c-1's MMA reads of stage (c+1)&1.
        __syncthreads();
        if (c + 1 < nch) load_regs(c + 1);     // LDGs in flight under the MMAs

        const uint32_t stg = sbase + (c & 1) * STAGE;
        #pragma unroll
        for (int ks = 0; ks < 2; ks++) {
            const int k0 = ks * 16;
            uint32_t ah[4][4], al[4][4], bh[4][2], bl[4][2];
            #pragma unroll
            for (int im = 0; im < 4; im++) {
                const uint32_t ad = stg + OFF_AH +
                    ((m0 + im * 16 + (lane & 15)) * A_ST + k0 + ((lane >> 4) & 1) * 8) * 2;
                ldsm_x4(ah[im], ad);
                ldsm_x4(al[im], ad + (OFF_AL - OFF_AH));
            }
            // B fragments: jn pairs fused into x4 loads (half the LDS instructions)
            #pragma unroll
            for (int p = 0; p < 2; p++) {
                const int g = lane >> 3;       // 0..3 -> matrix index
                uint32_t b4[4];
                uint32_t bd;
                if (!BTRANS) {
                    const int row = n0 + p * 16 + (g >> 1) * 8 + (lane & 7);
                    const int kc  = k0 + (g & 1) * 8;
                    bd = stg + OFF_BH + (row * A_ST + kc) * 2;
                    ldsm_x4(b4, bd);
                    bh[2*p][0] = b4[0]; bh[2*p][1] = b4[1];
                    bh[2*p+1][0] = b4[2]; bh[2*p+1][1] = b4[3];
                    ldsm_x4(b4, bd + (OFF_BL - OFF_BH));
                    bl[2*p][0] = b4[0]; bl[2*p][1] = b4[1];
                    bl[2*p+1][0] = b4[2]; bl[2*p+1][1] = b4[3];
                } else {
                    const int row = k0 + (g & 1) * 8 + (lane & 7);
                    const int col = n0 + p * 16 + (g >> 1) * 8;
                    bd = stg + OFF_BH + (row * BNN_ST + col) * 2;
                    ldsm_x4t(b4, bd);
                    bh[2*p][0] = b4[0]; bh[2*p][1] = b4[1];
                    bh[2*p+1][0] = b4[2]; bh[2*p+1][1] = b4[3];
                    ldsm_x4t(b4, bd + (OFF_BL - OFF_BH));
                    bl[2*p][0] = b4[0]; bl[2*p][1] = b4[1];
                    bl[2*p+1][0] = b4[2]; bl[2*p+1][1] = b4[3];
                }
            }
            #pragma unroll
            for (int im = 0; im < 4; im++)
                #pragma unroll
                for (int jn = 0; jn < 4; jn++) {
                    mma_bf16(acc[im][jn], ah[im], bh[jn]);   // hi*hi
                    mma_bf16(acc[im][jn], ah[im], bl[jn]);   // hi*lo
                    mma_bf16(acc[im][jn], al[im], bh[jn]);   // lo*hi
                }
        }

        if (c + 1 < nch) store_stage(c + 1);   // writes other stage; safe (see barrier)
    }

    // ---- epilogue ----
    const int r  = lane >> 2;
    const int cp = (lane & 3) * 2;
    #pragma unroll
    for (int im = 0; im < 4; im++) {
        #pragma unroll
        for (int jn = 0; jn < 4; jn++) {
            const int row = rowBase + m0 + im * 16 + r;
            const int col = colBase + n0 + jn * 8 + cp;
            *(float2*)(Cb + (size_t)row * ldc + col)       = make_float2(acc[im][jn][0], acc[im][jn][1]);
            *(float2*)(Cb + (size_t)(row + 8) * ldc + col) = make_float2(acc[im][jn][2], acc[im][jn][3]);
        }
    }
}

// ============================================================================
// Masked softmax over last dim, in place. One block per (b,t) row.
// ============================================================================
__device__ __forceinline__ float warpRedMax(float v) {
    #pragma unroll
    for (int o = 16; o > 0; o >>= 1) v = fmaxf(v, __shfl_xor_sync(0xffffffffu, v, o));
    return v;
}
__device__ __forceinline__ float warpRedSum(float v) {
    #pragma unroll
    for (int o = 16; o > 0; o >>= 1) v += __shfl_xor_sync(0xffffffffu, v, o);
    return v;
}

__global__ __launch_bounds__(256)
void softmax_kernel(float* __restrict__ S, const int* __restrict__ M)
{
    __shared__ float red[8];
    const int row = blockIdx.x;
    const int b   = row / T_DEC;
    float* x = S + (size_t)row * T_SRC;
    const int* m = M + (size_t)b * T_SRC;

    const int tid  = threadIdx.x;
    const int lane = tid & 31;
    const int wid  = tid >> 5;

    float v[8];
    float mx = -INFINITY;
    #pragma unroll
    for (int i = 0; i < 8; i++) {
        int s = tid + i * 256;
        float val = x[s];
        v[i] = (m[s] != 0) ? val : -INFINITY;
        mx = fmaxf(mx, v[i]);
    }
    mx = warpRedMax(mx);
    if (lane == 0) red[wid] = mx;
    __syncthreads();
    if (wid == 0) {
        float t = (lane < 8) ? red[lane] : -INFINITY;
        t = warpRedMax(t);
        if (lane == 0) red[0] = t;
    }
    __syncthreads();
    mx = red[0];

    float sum = 0.f;
    #pragma unroll
    for (int i = 0; i < 8; i++) {
        float e = __expf(v[i] - mx);
        v[i] = e;
        sum += e;
    }
    sum = warpRedSum(sum);
    __syncthreads();
    if (lane == 0) red[wid] = sum;
    __syncthreads();
    if (wid == 0) {
        float t = (lane < 8) ? red[lane] : 0.0f;
        t = warpRedSum(t);
        if (lane == 0) red[0] = t;
    }
    __syncthreads();
    const float inv = 1.0f / red[0];

    #pragma unroll
    for (int i = 0; i < 8; i++) {
        int s = tid + i * 256;
        x[s] = v[i] * inv;
    }
}

// ============================================================================
// Launch
// ============================================================================
extern "C" void kernel_launch(void* const* d_in, const int* in_sizes, int n_in,
                              void* d_out, int out_size)
{
    (void)in_sizes; (void)n_in; (void)out_size;
    const float* dec  = (const float*)d_in[0];   // [B, T_DEC, D]
    const float* enc  = (const float*)d_in[1];   // [B, T_SRC, D]
    const int*   mask = (const int*)d_in[2];     // [B, 1, T_SRC] bool -> int32

    float* ctx  = (float*)d_out;                              // [B, T_DEC, D]
    float* attn = (float*)d_out + (size_t)B * T_DEC * D;      // [B, T_DEC, T_SRC]

    cudaFuncSetAttribute(gemm_split<false>,
                         cudaFuncAttributeMaxDynamicSharedMemorySize, GEMM_SMEM);
    cudaFuncSetAttribute(gemm_split<true>,
                         cudaFuncAttributeMaxDynamicSharedMemorySize, GEMM_SMEM);

    // 1) scores = dec x enc^T   [M=T_DEC, N=T_SRC, K=D]   (B = enc[s,d], k-major)
    gemm_split<false><<<dim3(T_SRC / 128, T_DEC / 128, B), 256, GEMM_SMEM>>>(
        dec, enc, attn, D, D, T_SRC, D,
        (size_t)T_DEC * D, (size_t)T_SRC * D, (size_t)T_DEC * T_SRC);

    // 2) masked softmax in place
    softmax_kernel<<<B * T_DEC, 256>>>(attn, mask);

    // 3) context = attn x enc   [M=T_DEC, N=D, K=T_SRC]   (B = enc[s,d], n-major)
    gemm_split<true><<<dim3(D / 128, T_DEC / 128, B), 256, GEMM_SMEM>>>(
        attn, enc, ctx, T_SRC, D, D, T_SRC,
        (size_t)T_DEC * T_SRC, (size_t)T_SRC * D, (size_t)T_DEC * D);
}

// round 11
// speedup vs baseline: 2.5987x; 1.0869x over previous
#include <cuda_runtime.h>
#include <cuda_bf16.h>
#include <cstdint>
#include <math.h>

#define B 32
#define T_DEC 1024
#define T_SRC 2048
#define D 1024

// ============================================================================
// mma.sync / ldmatrix helpers (compute_103-safe: sm_80+ PTX only)
// ============================================================================
__device__ __forceinline__ uint32_t smem_u32(const void* p) {
    uint32_t a;
    asm("{ .reg .u64 t; cvta.to.shared.u64 t, %1; cvt.u32.u64 %0, t; }" : "=r"(a) : "l"(p));
    return a;
}
__device__ __forceinline__ void ldsm_x4(uint32_t r[4], uint32_t addr) {
    asm volatile("ldmatrix.sync.aligned.m8n8.x4.shared.b16 {%0,%1,%2,%3}, [%4];"
                 : "=r"(r[0]), "=r"(r[1]), "=r"(r[2]), "=r"(r[3]) : "r"(addr));
}
__device__ __forceinline__ void ldsm_x4t(uint32_t r[4], uint32_t addr) {
    asm volatile("ldmatrix.sync.aligned.m8n8.x4.trans.shared.b16 {%0,%1,%2,%3}, [%4];"
                 : "=r"(r[0]), "=r"(r[1]), "=r"(r[2]), "=r"(r[3]) : "r"(addr));
}
__device__ __forceinline__ void mma_bf16(float d[4], const uint32_t a[4], const uint32_t b[2]) {
    asm volatile(
        "mma.sync.aligned.m16n8k16.row.col.f32.bf16.bf16.f32 "
        "{%0,%1,%2,%3}, {%4,%5,%6,%7}, {%8,%9}, {%0,%1,%2,%3};"
        : "+f"(d[0]), "+f"(d[1]), "+f"(d[2]), "+f"(d[3])
        : "r"(a[0]), "r"(a[1]), "r"(a[2]), "r"(a[3]), "r"(b[0]), "r"(b[1]));
}

// split fp32 -> (hi, lo) bf16 pairs, packed 2-at-a-time into b32
__device__ __forceinline__ void split2(float x0, float x1, uint32_t& h, uint32_t& l) {
    __nv_bfloat16 h0 = __float2bfloat16(x0);
    __nv_bfloat16 h1 = __float2bfloat16(x1);
    __nv_bfloat16 l0 = __float2bfloat16(x0 - __bfloat162float(h0));
    __nv_bfloat16 l1 = __float2bfloat16(x1 - __bfloat162float(h1));
    __nv_bfloat162 hp = __nv_bfloat162(h0, h1);
    __nv_bfloat162 lp = __nv_bfloat162(l0, l1);
    h = *(uint32_t*)&hp;
    l = *(uint32_t*)&lp;
}

// ============================================================================
// Split-bf16 GEMM via mma.sync:  C[m,n] = sum_k A[m,k] * B(k,n)
//   BTRANS=false: B stored [n][k] (k contiguous)  -> NT (scores: B=enc[s,d])
//   BTRANS=true : B stored [k][n] (n contiguous)  -> NN (context: B=enc[s,d], k=s)
// CTA tile 128x64, BK=32, 8 warps (4Mx2N), warp tile 32x32, double-buffered,
// one barrier per chunk, 2 CTAs/SM for latency hiding.
// ============================================================================
#define BK 32
#define A_ST 40                        // padded row stride (elems), [128][32] A tiles
#define BNN_ST 72                      // padded row stride (elems), [32][64] B tile (BTRANS)
#define A_BYTES (128 * A_ST * 2)       // 10240
#define B_BYTES 5120                   // max(64*40*2, 32*72*2)
#define OFF_AH 0
#define OFF_AL (A_BYTES)               // 10240
#define OFF_BH (2 * A_BYTES)           // 20480
#define OFF_BL (2 * A_BYTES + B_BYTES) // 25600
#define STAGE  (2 * A_BYTES + 2 * B_BYTES)   // 30720
#define GEMM_SMEM (2 * STAGE)                // 61440

template <bool BTRANS>
__global__ __launch_bounds__(256, 2)
void gemm_split(const float* __restrict__ A, const float* __restrict__ Bm,
                float* __restrict__ C,
                int lda, int ldb, int ldc, int KK,
                size_t sA, size_t sB, size_t sC)
{
    extern __shared__ char dsm[];
    const uint32_t sbase = smem_u32(dsm);

    const int bz      = blockIdx.z;
    const int rowBase = blockIdx.y * 128;
    const int colBase = blockIdx.x * 64;

    const float* Ab = A  + (size_t)bz * sA + (size_t)rowBase * lda;
    const float* Bb = BTRANS ? (Bm + (size_t)bz * sB + colBase)
                             : (Bm + (size_t)bz * sB + (size_t)colBase * ldb);
    float*       Cb = C  + (size_t)bz * sC;

    const int tid  = threadIdx.x;
    const int lane = tid & 31;
    const int wid  = tid >> 5;
    const int m0   = (wid & 3) * 32;      // warp M offset (4 warps over 128)
    const int n0   = (wid >> 2) * 32;     // warp N offset (2 warps over 64)

    float acc[2][4][4];
    #pragma unroll
    for (int i = 0; i < 2; i++)
        #pragma unroll
        for (int j = 0; j < 4; j++)
            #pragma unroll
            for (int r = 0; r < 4; r++) acc[i][j][r] = 0.f;

    const int nch = KK / BK;
    float4 ra[4], rb[2];

    // ---- loaders ----
    auto load_regs = [&](int c) {
        const int kt = c * BK;
        #pragma unroll
        for (int q = 0; q < 4; q++) {      // A: [128][32] fp32 = 1024 float4
            const int f4 = tid + q * 256;
            const int row = f4 >> 3, kq = (f4 & 7) * 4;
            ra[q] = *(const float4*)(Ab + (size_t)row * lda + kt + kq);
        }
        #pragma unroll
        for (int q = 0; q < 2; q++) {      // B: 512 float4
            const int f4 = tid + q * 256;
            if (!BTRANS) {                 // [64 n][32 k]
                const int row = f4 >> 3, kq = (f4 & 7) * 4;
                rb[q] = *(const float4*)(Bb + (size_t)row * ldb + kt + kq);
            } else {                       // [32 k][64 n]
                const int kr = f4 >> 4, nq = (f4 & 15) * 4;
                rb[q] = *(const float4*)(Bb + (size_t)(kt + kr) * ldb + nq);
            }
        }
    };
    auto store_stage = [&](int c) {
        char* st = dsm + (c & 1) * STAGE;
        #pragma unroll
        for (int q = 0; q < 4; q++) {
            const int f4 = tid + q * 256;
            const int row = f4 >> 3, kq = (f4 & 7) * 4;
            uint32_t h01, l01, h23, l23;
            split2(ra[q].x, ra[q].y, h01, l01);
            split2(ra[q].z, ra[q].w, h23, l23);
            const int off = (row * A_ST + kq) * 2;
            *(uint2*)(st + OFF_AH + off) = make_uint2(h01, h23);
            *(uint2*)(st + OFF_AL + off) = make_uint2(l01, l23);
        }
        #pragma unroll
        for (int q = 0; q < 2; q++) {
            const int f4 = tid + q * 256;
            uint32_t h01, l01, h23, l23;
            split2(rb[q].x, rb[q].y, h01, l01);
            split2(rb[q].z, rb[q].w, h23, l23);
            int off;
            if (!BTRANS) { const int row = f4 >> 3, kq = (f4 & 7) * 4; off = (row * A_ST + kq) * 2; }
            else         { const int kr = f4 >> 4, nq = (f4 & 15) * 4; off = (kr * BNN_ST + nq) * 2; }
            *(uint2*)(st + OFF_BH + off) = make_uint2(h01, h23);
            *(uint2*)(st + OFF_BL + off) = make_uint2(l01, l23);
        }
    };

    load_regs(0);
    store_stage(0);

    for (int c = 0; c < nch; c++) {
        // Single barrier per chunk: proves (a) stage c&1 fully written,
        // (b) every warp finished chunk c-1's MMA reads of stage (c+1)&1.
        __syncthreads();
        if (c + 1 < nch) load_regs(c + 1);     // LDGs in flight under the MMAs

        const uint32_t stg = sbase + (c & 1) * STAGE;
        #pragma unroll
        for (int ks = 0; ks < 2; ks++) {
            const int k0 = ks * 16;
            uint32_t ah[2][4], al[2][4], bh[4][2], bl[4][2];
            #pragma unroll
            for (int im = 0; im < 2; im++) {
                const uint32_t ad = stg + OFF_AH +
                    ((m0 + im * 16 + (lane & 15)) * A_ST + k0 + ((lane >> 4) & 1) * 8) * 2;
                ldsm_x4(ah[im], ad);
                ldsm_x4(al[im], ad + (OFF_AL - OFF_AH));
            }
            // B fragments: jn pairs fused into x4 loads
            #pragma unroll
            for (int p = 0; p < 2; p++) {
                const int g = lane >> 3;       // 0..3 -> matrix index
                uint32_t b4[4];
                uint32_t bd;
                if (!BTRANS) {
                    const int row = n0 + p * 16 + (g >> 1) * 8 + (lane & 7);
                    const int kc  = k0 + (g & 1) * 8;
                    bd = stg + OFF_BH + (row * A_ST + kc) * 2;
                    ldsm_x4(b4, bd);
                    bh[2*p][0] = b4[0]; bh[2*p][1] = b4[1];
                    bh[2*p+1][0] = b4[2]; bh[2*p+1][1] = b4[3];
                    ldsm_x4(b4, bd + (OFF_BL - OFF_BH));
                    bl[2*p][0] = b4[0]; bl[2*p][1] = b4[1];
                    bl[2*p+1][0] = b4[2]; bl[2*p+1][1] = b4[3];
                } else {
                    const int row = k0 + (g & 1) * 8 + (lane & 7);
                    const int col = n0 + p * 16 + (g >> 1) * 8;
                    bd = stg + OFF_BH + (row * BNN_ST + col) * 2;
                    ldsm_x4t(b4, bd);
                    bh[2*p][0] = b4[0]; bh[2*p][1] = b4[1];
                    bh[2*p+1][0] = b4[2]; bh[2*p+1][1] = b4[3];
                    ldsm_x4t(b4, bd + (OFF_BL - OFF_BH));
                    bl[2*p][0] = b4[0]; bl[2*p][1] = b4[1];
                    bl[2*p+1][0] = b4[2]; bl[2*p+1][1] = b4[3];
                }
            }
            #pragma unroll
            for (int im = 0; im < 2; im++)
                #pragma unroll
                for (int jn = 0; jn < 4; jn++) {
                    mma_bf16(acc[im][jn], ah[im], bh[jn]);   // hi*hi
                    mma_bf16(acc[im][jn], ah[im], bl[jn]);   // hi*lo
                    mma_bf16(acc[im][jn], al[im], bh[jn]);   // lo*hi
                }
        }

        if (c + 1 < nch) store_stage(c + 1);   // writes other stage; safe (see barrier)
    }

    // ---- epilogue ----
    const int r  = lane >> 2;
    const int cp = (lane & 3) * 2;
    #pragma unroll
    for (int im = 0; im < 2; im++) {
        #pragma unroll
        for (int jn = 0; jn < 4; jn++) {
            const int row = rowBase + m0 + im * 16 + r;
            const int col = colBase + n0 + jn * 8 + cp;
            *(float2*)(Cb + (size_t)row * ldc + col)       = make_float2(acc[im][jn][0], acc[im][jn][1]);
            *(float2*)(Cb + (size_t)(row + 8) * ldc + col) = make_float2(acc[im][jn][2], acc[im][jn][3]);
        }
    }
}

// ============================================================================
// Masked softmax over last dim, in place. One block per (b,t) row.
// ============================================================================
__device__ __forceinline__ float warpRedMax(float v) {
    #pragma unroll
    for (int o = 16; o > 0; o >>= 1) v = fmaxf(v, __shfl_xor_sync(0xffffffffu, v, o));
    return v;
}
__device__ __forceinline__ float warpRedSum(float v) {
    #pragma unroll
    for (int o = 16; o > 0; o >>= 1) v += __shfl_xor_sync(0xffffffffu, v, o);
    return v;
}

__global__ __launch_bounds__(256)
void softmax_kernel(float* __restrict__ S, const int* __restrict__ M)
{
    __shared__ float red[8];
    const int row = blockIdx.x;
    const int b   = row / T_DEC;
    float* x = S + (size_t)row * T_SRC;
    const int* m = M + (size_t)b * T_SRC;

    const int tid  = threadIdx.x;
    const int lane = tid & 31;
    const int wid  = tid >> 5;

    float v[8];
    float mx = -INFINITY;
    #pragma unroll
    for (int i = 0; i < 8; i++) {
        int s = tid + i * 256;
        float val = x[s];
        v[i] = (m[s] != 0) ? val : -INFINITY;
        mx = fmaxf(mx, v[i]);
    }
    mx = warpRedMax(mx);
    if (lane == 0) red[wid] = mx;
    __syncthreads();
    if (wid == 0) {
        float t = (lane < 8) ? red[lane] : -INFINITY;
        t = warpRedMax(t);
        if (lane == 0) red[0] = t;
    }
    __syncthreads();
    mx = red[0];

    float sum = 0.f;
    #pragma unroll
    for (int i = 0; i < 8; i++) {
        float e = __expf(v[i] - mx);
        v[i] = e;
        sum += e;
    }
    sum = warpRedSum(sum);
    __syncthreads();
    if (lane == 0) red[wid] = sum;
    __syncthreads();
    if (wid == 0) {
        float t = (lane < 8) ? red[lane] : 0.0f;
        t = warpRedSum(t);
        if (lane == 0) red[0] = t;
    }
    __syncthreads();
    const float inv = 1.0f / red[0];

    #pragma unroll
    for (int i = 0; i < 8; i++) {
        int s = tid + i * 256;
        x[s] = v[i] * inv;
    }
}

// ============================================================================
// Launch
// ============================================================================
extern "C" void kernel_launch(void* const* d_in, const int* in_sizes, int n_in,
                              void* d_out, int out_size)
{
    (void)in_sizes; (void)n_in; (void)out_size;
    const float* dec  = (const float*)d_in[0];   // [B, T_DEC, D]
    const float* enc  = (const float*)d_in[1];   // [B, T_SRC, D]
    const int*   mask = (const int*)d_in[2];     // [B, 1, T_SRC] bool -> int32

    float* ctx  = (float*)d_out;                              // [B, T_DEC, D]
    float* attn = (float*)d_out + (size_t)B * T_DEC * D;      // [B, T_DEC, T_SRC]

    cudaFuncSetAttribute(gemm_split<false>,
                         cudaFuncAttributeMaxDynamicSharedMemorySize, GEMM_SMEM);
    cudaFuncSetAttribute(gemm_split<true>,
                         cudaFuncAttributeMaxDynamicSharedMemorySize, GEMM_SMEM);

    // 1) scores = dec x enc^T   [M=T_DEC, N=T_SRC, K=D]   (B = enc[s,d], k-major)
    gemm_split<false><<<dim3(T_SRC / 64, T_DEC / 128, B), 256, GEMM_SMEM>>>(
        dec, enc, attn, D, D, T_SRC, D,
        (size_t)T_DEC * D, (size_t)T_SRC * D, (size_t)T_DEC * T_SRC);

    // 2) masked softmax in place
    softmax_kernel<<<B * T_DEC, 256>>>(attn, mask);

    // 3) context = attn x enc   [M=T_DEC, N=D, K=T_SRC]   (B = enc[s,d], n-major)
    gemm_split<true><<<dim3(D / 64, T_DEC / 128, B), 256, GEMM_SMEM>>>(
        attn, enc, ctx, T_SRC, D, D, T_SRC,
        (size_t)T_DEC * T_SRC, (size_t)T_SRC * D, (size_t)T_DEC * D);
}

// round 12
// speedup vs baseline: 2.9510x; 1.1356x over previous
#include <cuda_runtime.h>
#include <cuda_bf16.h>
#include <cstdint>
#include <math.h>

#define B 32
#define T_DEC 1024
#define T_SRC 2048
#define D 1024

// ============================================================================
// mma.sync / ldmatrix helpers (compute_103-safe: sm_80+ PTX only)
// ============================================================================
__device__ __forceinline__ uint32_t smem_u32(const void* p) {
    uint32_t a;
    asm("{ .reg .u64 t; cvta.to.shared.u64 t, %1; cvt.u32.u64 %0, t; }" : "=r"(a) : "l"(p));
    return a;
}
__device__ __forceinline__ void ldsm_x4(uint32_t r[4], uint32_t addr) {
    asm volatile("ldmatrix.sync.aligned.m8n8.x4.shared.b16 {%0,%1,%2,%3}, [%4];"
                 : "=r"(r[0]), "=r"(r[1]), "=r"(r[2]), "=r"(r[3]) : "r"(addr));
}
__device__ __forceinline__ void ldsm_x4t(uint32_t r[4], uint32_t addr) {
    asm volatile("ldmatrix.sync.aligned.m8n8.x4.trans.shared.b16 {%0,%1,%2,%3}, [%4];"
                 : "=r"(r[0]), "=r"(r[1]), "=r"(r[2]), "=r"(r[3]) : "r"(addr));
}
__device__ __forceinline__ void mma_bf16(float d[4], const uint32_t a[4], const uint32_t b[2]) {
    asm volatile(
        "mma.sync.aligned.m16n8k16.row.col.f32.bf16.bf16.f32 "
        "{%0,%1,%2,%3}, {%4,%5,%6,%7}, {%8,%9}, {%0,%1,%2,%3};"
        : "+f"(d[0]), "+f"(d[1]), "+f"(d[2]), "+f"(d[3])
        : "r"(a[0]), "r"(a[1]), "r"(a[2]), "r"(a[3]), "r"(b[0]), "r"(b[1]));
}

// split fp32 -> (hi, lo) bf16 pairs, packed 2-at-a-time into b32
__device__ __forceinline__ void split2(float x0, float x1, uint32_t& h, uint32_t& l) {
    __nv_bfloat16 h0 = __float2bfloat16(x0);
    __nv_bfloat16 h1 = __float2bfloat16(x1);
    __nv_bfloat16 l0 = __float2bfloat16(x0 - __bfloat162float(h0));
    __nv_bfloat16 l1 = __float2bfloat16(x1 - __bfloat162float(h1));
    __nv_bfloat162 hp = __nv_bfloat162(h0, h1);
    __nv_bfloat162 lp = __nv_bfloat162(l0, l1);
    h = *(uint32_t*)&hp;
    l = *(uint32_t*)&lp;
}

// ============================================================================
// Split-bf16 GEMM via mma.sync:  C[m,n] = sum_k A[m,k] * B(k,n)
//   BTRANS=false: B stored [n][k] (k contiguous)  -> NT (scores: B=enc[s,d])
//   BTRANS=true : B stored [k][n] (n contiguous)  -> NN (context: B=enc[s,d], k=s)
// CTA tile 128x128, 128 threads, 4 warps (2Mx2N), warp tile 64x64, BK=16,
// double-buffered, one barrier per chunk, 2 CTAs/SM.
// Big warp tiles minimize L1 fragment traffic (~85B/MMA ldmatrix);
// 2 independent CTAs/SM overlap one CTA's store phase with the other's MMAs.
// ============================================================================
#define BK 16
#define A_ST 24                        // elems: 16 data + 8 pad (48B stride, conflict-free)
#define BNN_ST 136                     // elems: [16][128] B tile (BTRANS), 272B stride
#define REG_B 6144                     // bytes per component region
#define OFF_AH 0
#define OFF_AL (REG_B)                 // 6144
#define OFF_BH (2 * REG_B)             // 12288
#define OFF_BL (3 * REG_B)             // 18432
#define STAGE  (4 * REG_B)             // 24576
#define GEMM_SMEM (2 * STAGE)          // 49152

template <bool BTRANS>
__global__ __launch_bounds__(128, 2)
void gemm_split(const float* __restrict__ A, const float* __restrict__ Bm,
                float* __restrict__ C,
                int lda, int ldb, int ldc, int KK,
                size_t sA, size_t sB, size_t sC)
{
    extern __shared__ char dsm[];
    const uint32_t sbase = smem_u32(dsm);

    const int bz      = blockIdx.z;
    const int rowBase = blockIdx.y * 128;
    const int colBase = blockIdx.x * 128;

    const float* Ab = A  + (size_t)bz * sA + (size_t)rowBase * lda;
    const float* Bb = BTRANS ? (Bm + (size_t)bz * sB + colBase)
                             : (Bm + (size_t)bz * sB + (size_t)colBase * ldb);
    float*       Cb = C  + (size_t)bz * sC;

    const int tid  = threadIdx.x;
    const int lane = tid & 31;
    const int wid  = tid >> 5;            // 0..3
    const int m0   = (wid >> 1) * 64;     // 2 warps over M=128
    const int n0   = (wid & 1) * 64;      // 2 warps over N=128

    float acc[4][8][4];
    #pragma unroll
    for (int i = 0; i < 4; i++)
        #pragma unroll
        for (int j = 0; j < 8; j++)
            #pragma unroll
            for (int r = 0; r < 4; r++) acc[i][j][r] = 0.f;

    const int nch = KK / BK;
    float4 ra[4], rb[4];

    // ---- loaders (128 threads, 512 float4 per tile -> 4 per thread) ----
    auto load_regs = [&](int c) {
        const int kt = c * BK;
        #pragma unroll
        for (int q = 0; q < 4; q++) {      // A: [128][16] fp32
            const int f4 = tid + q * 128;
            const int row = f4 >> 2, kq = (f4 & 3) * 4;
            ra[q] = *(const float4*)(Ab + (size_t)row * lda + kt + kq);
        }
        #pragma unroll
        for (int q = 0; q < 4; q++) {      // B: 512 float4
            const int f4 = tid + q * 128;
            if (!BTRANS) {                 // [128 n][16 k]
                const int row = f4 >> 2, kq = (f4 & 3) * 4;
                rb[q] = *(const float4*)(Bb + (size_t)row * ldb + kt + kq);
            } else {                       // [16 k][128 n]
                const int kr = f4 >> 5, nq = (f4 & 31) * 4;
                rb[q] = *(const float4*)(Bb + (size_t)(kt + kr) * ldb + nq);
            }
        }
    };
    auto store_stage = [&](int c) {
        char* st = dsm + (c & 1) * STAGE;
        #pragma unroll
        for (int q = 0; q < 4; q++) {
            const int f4 = tid + q * 128;
            const int row = f4 >> 2, kq = (f4 & 3) * 4;
            uint32_t h01, l01, h23, l23;
            split2(ra[q].x, ra[q].y, h01, l01);
            split2(ra[q].z, ra[q].w, h23, l23);
            const int off = (row * A_ST + kq) * 2;
            *(uint2*)(st + OFF_AH + off) = make_uint2(h01, h23);
            *(uint2*)(st + OFF_AL + off) = make_uint2(l01, l23);
        }
        #pragma unroll
        for (int q = 0; q < 4; q++) {
            const int f4 = tid + q * 128;
            uint32_t h01, l01, h23, l23;
            split2(rb[q].x, rb[q].y, h01, l01);
            split2(rb[q].z, rb[q].w, h23, l23);
            int off;
            if (!BTRANS) { const int row = f4 >> 2, kq = (f4 & 3) * 4; off = (row * A_ST + kq) * 2; }
            else         { const int kr = f4 >> 5, nq = (f4 & 31) * 4; off = (kr * BNN_ST + nq) * 2; }
            *(uint2*)(st + OFF_BH + off) = make_uint2(h01, h23);
            *(uint2*)(st + OFF_BL + off) = make_uint2(l01, l23);
        }
    };

    load_regs(0);
    store_stage(0);

    for (int c = 0; c < nch; c++) {
        // Single barrier per chunk: proves (a) stage c&1 fully written,
        // (b) every warp finished chunk c-1's MMA reads of stage (c+1)&1.
        __syncthreads();
        if (c + 1 < nch) load_regs(c + 1);     // LDGs in flight under the MMAs

        const uint32_t stg = sbase + (c & 1) * STAGE;

        // A fragments: 4 m16 blocks covering warp's 64 rows, k=0..16
        uint32_t ah[4][4], al[4][4];
        #pragma unroll
        for (int im = 0; im < 4; im++) {
            const uint32_t ad = stg + OFF_AH +
                ((m0 + im * 16 + (lane & 15)) * A_ST + ((lane >> 4) & 1) * 8) * 2;
            ldsm_x4(ah[im], ad);
            ldsm_x4(al[im], ad + (OFF_AL - OFF_AH));
        }

        // B fragments + MMAs, in 4 pair-groups (keeps b-frag register span small)
        #pragma unroll
        for (int p = 0; p < 4; p++) {
            const int g = lane >> 3;           // 0..3 -> matrix index within x4
            uint32_t bh4[4], bl4[4];
            if (!BTRANS) {
                const int row = n0 + p * 16 + (g >> 1) * 8 + (lane & 7);
                const int kc  = (g & 1) * 8;
                const uint32_t bd = stg + OFF_BH + (row * A_ST + kc) * 2;
                ldsm_x4(bh4, bd);
                ldsm_x4(bl4, bd + (OFF_BL - OFF_BH));
            } else {
                const int row = (g & 1) * 8 + (lane & 7);
                const int col = n0 + p * 16 + (g >> 1) * 8;
                const uint32_t bd = stg + OFF_BH + (row * BNN_ST + col) * 2;
                ldsm_x4t(bh4, bd);
                ldsm_x4t(bl4, bd + (OFF_BL - OFF_BH));
            }
            uint32_t bh[2][2] = {{bh4[0], bh4[1]}, {bh4[2], bh4[3]}};
            uint32_t bl[2][2] = {{bl4[0], bl4[1]}, {bl4[2], bl4[3]}};
            #pragma unroll
            for (int im = 0; im < 4; im++)
                #pragma unroll
                for (int j = 0; j < 2; j++) {
                    float* a = acc[im][2 * p + j];
                    mma_bf16(a, ah[im], bh[j]);   // hi*hi
                    mma_bf16(a, ah[im], bl[j]);   // hi*lo
                    mma_bf16(a, al[im], bh[j]);   // lo*hi
                }
        }

        if (c + 1 < nch) store_stage(c + 1);   // writes other stage; safe (see barrier)
    }

    // ---- epilogue ----
    const int r  = lane >> 2;
    const int cp = (lane & 3) * 2;
    #pragma unroll
    for (int im = 0; im < 4; im++) {
        #pragma unroll
        for (int jn = 0; jn < 8; jn++) {
            const int row = rowBase + m0 + im * 16 + r;
            const int col = colBase + n0 + jn * 8 + cp;
            *(float2*)(Cb + (size_t)row * ldc + col)       = make_float2(acc[im][jn][0], acc[im][jn][1]);
            *(float2*)(Cb + (size_t)(row + 8) * ldc + col) = make_float2(acc[im][jn][2], acc[im][jn][3]);
        }
    }
}

// ============================================================================
// Masked softmax over last dim, in place. One block per (b,t) row.
// ============================================================================
__device__ __forceinline__ float warpRedMax(float v) {
    #pragma unroll
    for (int o = 16; o > 0; o >>= 1) v = fmaxf(v, __shfl_xor_sync(0xffffffffu, v, o));
    return v;
}
__device__ __forceinline__ float warpRedSum(float v) {
    #pragma unroll
    for (int o = 16; o > 0; o >>= 1) v += __shfl_xor_sync(0xffffffffu, v, o);
    return v;
}

__global__ __launch_bounds__(256)
void softmax_kernel(float* __restrict__ S, const int* __restrict__ M)
{
    __shared__ float red[8];
    const int row = blockIdx.x;
    const int b   = row / T_DEC;
    float* x = S + (size_t)row * T_SRC;
    const int* m = M + (size_t)b * T_SRC;

    const int tid  = threadIdx.x;
    const int lane = tid & 31;
    const int wid  = tid >> 5;

    float v[8];
    float mx = -INFINITY;
    #pragma unroll
    for (int i = 0; i < 8; i++) {
        int s = tid + i * 256;
        float val = x[s];
        v[i] = (m[s] != 0) ? val : -INFINITY;
        mx = fmaxf(mx, v[i]);
    }
    mx = warpRedMax(mx);
    if (lane == 0) red[wid] = mx;
    __syncthreads();
    if (wid == 0) {
        float t = (lane < 8) ? red[lane] : -INFINITY;
        t = warpRedMax(t);
        if (lane == 0) red[0] = t;
    }
    __syncthreads();
    mx = red[0];

    float sum = 0.f;
    #pragma unroll
    for (int i = 0; i < 8; i++) {
        float e = __expf(v[i] - mx);
        v[i] = e;
        sum += e;
    }
    sum = warpRedSum(sum);
    __syncthreads();
    if (lane == 0) red[wid] = sum;
    __syncthreads();
    if (wid == 0) {
        float t = (lane < 8) ? red[lane] : 0.0f;
        t = warpRedSum(t);
        if (lane == 0) red[0] = t;
    }
    __syncthreads();
    const float inv = 1.0f / red[0];

    #pragma unroll
    for (int i = 0; i < 8; i++) {
        int s = tid + i * 256;
        x[s] = v[i] * inv;
    }
}

// ============================================================================
// Launch
// ============================================================================
extern "C" void kernel_launch(void* const* d_in, const int* in_sizes, int n_in,
                              void* d_out, int out_size)
{
    (void)in_sizes; (void)n_in; (void)out_size;
    const float* dec  = (const float*)d_in[0];   // [B, T_DEC, D]
    const float* enc  = (const float*)d_in[1];   // [B, T_SRC, D]
    const int*   mask = (const int*)d_in[2];     // [B, 1, T_SRC] bool -> int32

    float* ctx  = (float*)d_out;                              // [B, T_DEC, D]
    float* attn = (float*)d_out + (size_t)B * T_DEC * D;      // [B, T_DEC, T_SRC]

    cudaFuncSetAttribute(gemm_split<false>,
                         cudaFuncAttributeMaxDynamicSharedMemorySize, GEMM_SMEM);
    cudaFuncSetAttribute(gemm_split<true>,
                         cudaFuncAttributeMaxDynamicSharedMemorySize, GEMM_SMEM);

    // 1) scores = dec x enc^T   [M=T_DEC, N=T_SRC, K=D]   (B = enc[s,d], k-major)
    gemm_split<false><<<dim3(T_SRC / 128, T_DEC / 128, B), 128, GEMM_SMEM>>>(
        dec, enc, attn, D, D, T_SRC, D,
        (size_t)T_DEC * D, (size_t)T_SRC * D, (size_t)T_DEC * T_SRC);

    // 2) masked softmax in place
    softmax_kernel<<<B * T_DEC, 256>>>(attn, mask);

    // 3) context = attn x enc   [M=T_DEC, N=D, K=T_SRC]   (B = enc[s,d], n-major)
    gemm_split<true><<<dim3(D / 128, T_DEC / 128, B), 128, GEMM_SMEM>>>(
        attn, enc, ctx, T_SRC, D, D, T_SRC,
        (size_t)T_DEC * T_SRC, (size_t)T_SRC * D, (size_t)T_DEC * D);
}